// round 4
// baseline (speedup 1.0000x reference)
#include <cuda_runtime.h>
#include <string.h>

// Problem constants (B, D, H, W, K) = (32, 256, 64, 64, 64)
constexpr int Bn  = 32;
constexpr int Dd  = 256;
constexpr int Nn  = 4096;     // H*W
constexpr int Kk  = 64;
constexpr int NC  = 64;       // n-rows per chunk
constexpr int CH  = 8;        // chunks per CTA
constexpr int NCH = Nn / (NC * CH);   // 8 CTAs along n per batch
constexpr int NTH = 256;

// smem layout (float words)
constexpr int XS_W = NC * Dd;        // 16384 swizzled X tile [n][d]
constexpr int CS_W = Kk * Dd;        // 16384 swizzled normalized codewords [k][d]
constexpr int PS_W = NC * Kk;        // 4096  raw logits P[n][k]
constexpr int A2_W = NC * Kk * 2;    // 8192  duplicated softmax A as float2 {a,a}
constexpr int SMEM_WORDS = XS_W + CS_W + PS_W + A2_W;     // 45056
constexpr int SMEM_BYTES = SMEM_WORDS * 4;                // 180224

typedef unsigned long long ull;

__device__ float g_Cn[Kk * Dd];                    // normalized codewords (k-major)
__device__ float g_S [Bn * Kk];                    // sum_n A[b,n,k]
__device__ float g_part[(size_t)Bn * NCH * Kk * Dd];  // 16 MB partial E

#define FMA2(acc, a, b) asm("fma.rn.f32x2 %0, %1, %2, %0;" : "+l"(acc) : "l"(a), "l"(b))

static __device__ __forceinline__ float2 unpack2(ull v) {
    float2 f;
    asm("mov.b64 {%0,%1}, %2;" : "=f"(f.x), "=f"(f.y) : "l"(v));
    return f;
}

// ---------------- prep: normalize codewords, zero g_S ----------------
__global__ void prep_kernel(const float* __restrict__ C) {
    int t = blockIdx.x * blockDim.x + threadIdx.x;   // 0..2047
    if (t < Bn * Kk) g_S[t] = 0.f;
    int k = t >> 5;            // one warp per codeword, k in [0,64)
    int l = t & 31;
    const float* row = C + k * Dd;
    float v[8];
    float ss = 0.f;
#pragma unroll
    for (int j = 0; j < 8; j++) { v[j] = row[l + 32 * j]; ss += v[j] * v[j]; }
#pragma unroll
    for (int o = 16; o > 0; o >>= 1) ss += __shfl_xor_sync(0xffffffffu, ss, o);
    float rs = 1.f / fmaxf(sqrtf(ss), 1e-8f);
#pragma unroll
    for (int j = 0; j < 8; j++) g_Cn[k * Dd + l + 32 * j] = v[j] * rs;
}

// ---------------- main fused kernel ----------------
__global__ __launch_bounds__(NTH, 1) void main_kernel(const float* __restrict__ X) {
    extern __shared__ float sm[];
    float* Xs  = sm;                       // swizzled: word n*256 + (d ^ 2*(n&15))
    float* Cs  = Xs + XS_W;                // swizzled: word k*256 + (d ^ 2*((k>>2)&15))
    float* Ps  = Cs + CS_W;                // P[n][k]
    float* A2s = Ps + PS_W;                // float2 dup A at f2-index n*64 + k

    const int b = blockIdx.y;
    const int g = blockIdx.x;
    const int t = threadIdx.x;
    const int w = t >> 5;
    const int l = t & 31;

    // load normalized codewords into swizzled smem
    for (int i = t; i < Kk * Dd; i += NTH) {
        int k = i >> 8, d = i & 255;
        Cs[k * 256 + (d ^ (2 * ((k >> 2) & 15)))] = g_Cn[i];
    }

    ull Eacc[8][4];                        // [kk][jj] packed float2 over d pairs
#pragma unroll
    for (int kk = 0; kk < 8; kk++)
#pragma unroll
        for (int jj = 0; jj < 4; jj++) Eacc[kk][jj] = 0ull;

    float sA0 = 0.f, sA1 = 0.f;
    const float* Xb = X + (size_t)b * Dd * Nn;

    for (int c = 0; c < CH; c++) {
        const int n0 = (g * CH + c) * NC;
        __syncthreads();
        // ---- transpose-load X chunk: Xs[n][d] = X[b][d][n0+n] ----
#pragma unroll 4
        for (int i = 0; i < 64; i++) {
            int idx = i * NTH + t;
            int d = idx >> 6, n = idx & 63;
            Xs[n * 256 + (d ^ (2 * (n & 15)))] = Xb[(size_t)d * Nn + n0 + n];
        }
        __syncthreads();

        // ---- row norms: warp w owns rows w*8 .. w*8+7 ----
        float rno[8];
        const float2* X2c = (const float2*)Xs;
#pragma unroll
        for (int r = 0; r < 8; r++) {
            int n = w * 8 + r;
            int sx = n & 15;
            float ss = 0.f;
#pragma unroll
            for (int jj = 0; jj < 4; jj++) {
                float2 v = X2c[n * 128 + ((l ^ sx) + 32 * jj)];
                ss += v.x * v.x + v.y * v.y;
            }
#pragma unroll
            for (int o = 16; o > 0; o >>= 1) ss += __shfl_xor_sync(0xffffffffu, ss, o);
            rno[r] = 1.f / fmaxf(sqrtf(ss), 1e-8f);
        }

        // ---- L matmul: P[n][k] = sum_d Xf[n][d] * Cn[k][d] (f32x2 over d) ----
        {
            const int n0t = (t >> 4) * 4;
            const int k0t = (t & 15) * 4;
            ull acc[4][4];
#pragma unroll
            for (int i = 0; i < 4; i++)
#pragma unroll
                for (int j = 0; j < 4; j++) acc[i][j] = 0ull;

            const ull* Xu = (const ull*)Xs;
            const ull* Cu = (const ull*)Cs;
#pragma unroll 2
            for (int dp = 0; dp < 128; dp++) {
                ull xv[4], cv[4];
#pragma unroll
                for (int i = 0; i < 4; i++) {
                    int n = n0t + i;
                    xv[i] = Xu[n * 128 + (dp ^ (n & 15))];
                }
#pragma unroll
                for (int j = 0; j < 4; j++) {
                    int k = k0t + j;
                    cv[j] = Cu[k * 128 + (dp ^ ((k >> 2) & 15))];
                }
#pragma unroll
                for (int i = 0; i < 4; i++)
#pragma unroll
                    for (int j = 0; j < 4; j++) FMA2(acc[i][j], xv[i], cv[j]);
            }
#pragma unroll
            for (int i = 0; i < 4; i++)
#pragma unroll
                for (int j = 0; j < 4; j++) {
                    float2 f = unpack2(acc[i][j]);
                    Ps[(n0t + i) * 64 + k0t + j] = f.x + f.y;
                }
        }
        __syncthreads();

        // ---- softmax over k (warp-row, temperature = 1/||x||) ----
#pragma unroll
        for (int r = 0; r < 8; r++) {
            int n = w * 8 + r;
            float p0 = Ps[n * 64 + l]      * rno[r];
            float p1 = Ps[n * 64 + l + 32] * rno[r];
            float m = fmaxf(p0, p1);
#pragma unroll
            for (int o = 16; o > 0; o >>= 1) m = fmaxf(m, __shfl_xor_sync(0xffffffffu, m, o));
            float e0 = __expf(p0 - m);
            float e1 = __expf(p1 - m);
            float s = e0 + e1;
#pragma unroll
            for (int o = 16; o > 0; o >>= 1) s += __shfl_xor_sync(0xffffffffu, s, o);
            float inv = 1.f / s;
            float a0 = e0 * inv, a1 = e1 * inv;
            sA0 += a0; sA1 += a1;
            float2* A2 = (float2*)A2s;
            A2[n * 64 + l]      = make_float2(a0, a0);
            A2[n * 64 + l + 32] = make_float2(a1, a1);
        }
        __syncthreads();

        // ---- aggregate: E[k][d] += sum_n A[n][k] * Xf[n][d] ----
        {
            const ull* Xu = (const ull*)Xs;
            const ulonglong2* A16 = (const ulonglong2*)A2s;
#pragma unroll 2
            for (int n = 0; n < NC; n++) {
                int sx = n & 15;
                ull xv[4];
#pragma unroll
                for (int jj = 0; jj < 4; jj++)
                    xv[jj] = Xu[n * 128 + ((l ^ sx) + 32 * jj)];
                ull av[8];
#pragma unroll
                for (int q = 0; q < 4; q++) {
                    ulonglong2 p = A16[n * 32 + w * 4 + q];
                    av[2 * q]     = p.x;
                    av[2 * q + 1] = p.y;
                }
#pragma unroll
                for (int kk = 0; kk < 8; kk++)
#pragma unroll
                    for (int jj = 0; jj < 4; jj++) FMA2(Eacc[kk][jj], av[kk], xv[jj]);
            }
        }
    }

    // ---- flush partial E to scratch (no atomics) ----
    float2* P2 = (float2*)(g_part + ((size_t)(b * NCH + g)) * Kk * Dd);
#pragma unroll
    for (int kk = 0; kk < 8; kk++) {
        int k = w * 8 + kk;
#pragma unroll
        for (int jj = 0; jj < 4; jj++) {
            int d = 2 * l + 64 * jj;
            P2[(k * Dd + d) >> 1] = unpack2(Eacc[kk][jj]);
        }
    }
    atomicAdd(&g_S[b * Kk + l],      sA0);
    atomicAdd(&g_S[b * Kk + l + 32], sA1);
}

// ---------------- finalize: reduce partials, subtract S*C ----------------
__global__ void fin_kernel(const float* __restrict__ Craw, float* __restrict__ out) {
    int i = blockIdx.x * blockDim.x + threadIdx.x;   // float4 index, 131072 total
    int idx = i * 4;
    int b = idx >> 14;              // / (K*D)
    int r = idx & 16383;
    int k = r >> 8;
    const float4* Pp = (const float4*)g_part;
    int stride4 = (Kk * Dd) >> 2;
    int base = b * NCH * stride4 + (r >> 2);
    float4 s = make_float4(0.f, 0.f, 0.f, 0.f);
#pragma unroll
    for (int g = 0; g < NCH; g++) {
        float4 p = Pp[base + g * stride4];
        s.x += p.x; s.y += p.y; s.z += p.z; s.w += p.w;
    }
    float Sv = g_S[b * Kk + k];
    float4 c = ((const float4*)Craw)[r >> 2];
    s.x -= Sv * c.x; s.y -= Sv * c.y; s.z -= Sv * c.z; s.w -= Sv * c.w;
    ((float4*)out)[i] = s;
}

extern "C" void kernel_launch(void* const* d_in, const int* in_sizes, int n_in,
                              void* d_out, int out_size) {
    const float* X = (const float*)d_in[0];
    const float* C = (const float*)d_in[1];
    float* out = (float*)d_out;

    cudaFuncSetAttribute(main_kernel, cudaFuncAttributeMaxDynamicSharedMemorySize, SMEM_BYTES);

    prep_kernel<<<2, 1024>>>(C);
    main_kernel<<<dim3(NCH, Bn), NTH, SMEM_BYTES>>>(X);
    fin_kernel<<<(Bn * Kk * Dd / 4 + 255) / 256, 256>>>(C, out);
}

// round 13
// speedup vs baseline: 3.8926x; 3.8926x over previous
#include <cuda_runtime.h>
#include <cstdint>

// Problem: B=32, D=256, N=4096 (H*W), K=64
constexpr int Bn = 32, Dd = 256, Nn = 4096, Kk = 64;
constexpr int TN = 128, TILES = 8, GN = 4, NTH = 256;

// smem float-word offsets
constexpr int XS = 0;          // Xs [128n][256d], xor-swizzled, 32768 words
constexpr int CT = 32768;      // Ct [64k][256d], xor-swizzled, 16384 words
constexpr int AT = 49152;      // At [64k][stride 132], 8448 words
constexpr int SMW = 57600;
constexpr int SMEM_BYTES = SMW * 4;   // 230400 <= 232448

__device__ float g_Cn[Kk * Dd];                        // normalized codewords (tf32)
__device__ float g_S[Bn * Kk];                         // sum_n A[b,n,k]
__device__ float g_part[(size_t)Bn * GN * Kk * Dd];   // 8MB per-CTA slabs [k][d]

static __device__ __forceinline__ uint32_t tf32c(float f) {
    uint32_t r;
    asm("cvt.rna.tf32.f32 %0, %1;" : "=r"(r) : "f"(f));
    return r;
}

// D += A(16x8) * B(8x8), tf32 inputs, f32 accumulate
static __device__ __forceinline__ void mma8(float* d, const uint32_t* a, const uint32_t* b) {
    asm volatile("mma.sync.aligned.m16n8k8.row.col.f32.tf32.tf32.f32 "
                 "{%0,%1,%2,%3}, {%4,%5,%6,%7}, {%8,%9}, {%0,%1,%2,%3};"
                 : "+f"(d[0]), "+f"(d[1]), "+f"(d[2]), "+f"(d[3])
                 : "r"(a[0]), "r"(a[1]), "r"(a[2]), "r"(a[3]), "r"(b[0]), "r"(b[1]));
}

// ---------------- prep: normalize codewords (tf32-rounded), zero g_S ----------------
__global__ void prep_kernel(const float* __restrict__ C) {
    int t = blockIdx.x * blockDim.x + threadIdx.x;   // 0..2047
    if (t < Bn * Kk) g_S[t] = 0.f;
    int k = t >> 5, l = t & 31;
    const float* row = C + k * Dd;
    float v[8], ss = 0.f;
#pragma unroll
    for (int j = 0; j < 8; j++) { v[j] = row[l + 32 * j]; ss += v[j] * v[j]; }
#pragma unroll
    for (int o = 16; o > 0; o >>= 1) ss += __shfl_xor_sync(0xffffffffu, ss, o);
    float rs = 1.f / fmaxf(sqrtf(ss), 1e-8f);
#pragma unroll
    for (int j = 0; j < 8; j++)
        g_Cn[k * Dd + l + 32 * j] = __uint_as_float(tf32c(v[j] * rs));
}

// ---------------- main fused kernel (mma.sync tf32) ----------------
__global__ __launch_bounds__(NTH, 1) void main_kernel(const float* __restrict__ X) {
    extern __shared__ float sm[];
    float*    Xs  = sm + XS;
    float*    Ct  = sm + CT;
    float*    Atm = sm + AT;
    uint32_t* XsU = (uint32_t*)Xs;
    uint32_t* CtU = (uint32_t*)Ct;
    uint32_t* AtU = (uint32_t*)Atm;

    const int b = blockIdx.y, gx = blockIdx.x;
    const int t = threadIdx.x, w = t >> 5, lane = t & 31;
    const int gid = lane >> 2, tig = lane & 3;
    const float* Xb = X + (size_t)b * Dd * Nn;

    // fill Ct: Ct[k][d ^ 4*(k&7)]
    for (int i = t; i < Kk * Dd; i += NTH) {
        int k = i >> 8, d = i & 255;
        Ct[k * 256 + (d ^ ((k & 7) << 2))] = g_Cn[i];
    }

    // GEMM1 warp map: p = row-pair (32 n), h = k-half (32 k)
    const int p = w & 3, h = w >> 2;
    const int M0 = p * 32, kb = h * 32;
    // GEMM2 warp map: mh = k-half (32 k rows), dq = d-quarter (64 d cols)
    const int mh = w & 1, dq = w >> 1;
    const int K0 = mh * 32, db = dq * 64;

    float E2[2][8][4];   // persistent E^T accumulators
#pragma unroll
    for (int i = 0; i < 2; i++)
#pragma unroll
        for (int j = 0; j < 8; j++)
#pragma unroll
            for (int q = 0; q < 4; q++) E2[i][j][q] = 0.f;
    float sS = 0.f;

    for (int tau = 0; tau < TILES; tau++) {
        const int n0 = (gx * TILES + tau) * TN;
        __syncthreads();   // Xs / At reusable (prev GEMM2 + S-fold done)

        // ---- load Xs[n][d] = tf32(X[b][d][n0+n]), coalesced LDG + STS.128 ----
        {
            const int gq = t >> 7, nl = t & 127;
            const uint32_t swn = (nl & 7) << 2;
#pragma unroll 4
            for (int r = 0; r < 256; r += 8) {
                int d0 = r + gq * 4;
                const float* src = Xb + (size_t)d0 * Nn + n0 + nl;
                uint4 o;
                o.x = tf32c(src[0]);
                o.y = tf32c(src[Nn]);
                o.z = tf32c(src[2 * Nn]);
                o.w = tf32c(src[3 * Nn]);
                *(uint4*)(XsU + nl * 256 + ((uint32_t)d0 ^ swn)) = o;
            }
        }
        __syncthreads();

        // ---- GEMM1: L[n][k] = sum_d Xs[n][d] * Ct[k][d], frags -> At[k][n] ----
        {
            float D1[2][4][4];
#pragma unroll
            for (int i = 0; i < 2; i++)
#pragma unroll
                for (int j = 0; j < 4; j++)
#pragma unroll
                    for (int q = 0; q < 4; q++) D1[i][j][q] = 0.f;

            const uint32_t swA = (uint32_t)gid << 2;
#pragma unroll 4
            for (int s = 0; s < 32; s++) {
                const uint32_t c0 = 8 * s + tig;
                const uint32_t t1 = c0 ^ swA, t2 = t1 ^ 4u;
                uint32_t A[2][4], Bf[4][2];
#pragma unroll
                for (int mt = 0; mt < 2; mt++) {
                    const uint32_t* rp = XsU + (M0 + 16 * mt + gid) * 256;
                    A[mt][0] = rp[t1];        A[mt][1] = rp[2048 + t1];
                    A[mt][2] = rp[t2];        A[mt][3] = rp[2048 + t2];
                }
#pragma unroll
                for (int kt = 0; kt < 4; kt++) {
                    const uint32_t* cp = CtU + (kb + 8 * kt + gid) * 256;
                    Bf[kt][0] = cp[t1];       Bf[kt][1] = cp[t2];
                }
#pragma unroll
                for (int mt = 0; mt < 2; mt++)
#pragma unroll
                    for (int kt = 0; kt < 4; kt++)
                        mma8(D1[mt][kt], A[mt], Bf[kt]);
            }
            // transpose-store raw logits into At[k][n] (conflict-free)
#pragma unroll
            for (int mt = 0; mt < 2; mt++)
#pragma unroll
                for (int kt = 0; kt < 4; kt++) {
                    int kq = kb + 8 * kt + 2 * tig;
                    int nq = M0 + 16 * mt + gid;
                    Atm[kq * 132 + nq]           = D1[mt][kt][0];
                    Atm[(kq + 1) * 132 + nq]     = D1[mt][kt][1];
                    Atm[kq * 132 + nq + 8]       = D1[mt][kt][2];
                    Atm[(kq + 1) * 132 + nq + 8] = D1[mt][kt][3];
                }
        }
        __syncthreads();

        // ---- softmax over k (thread t<128 owns row n=t), in-place in At ----
        if (t < 128) {
            const uint32_t swn = (t & 7) << 2;
            float ss = 0.f;
#pragma unroll
            for (int j = 0; j < 64; j++) {
                float4 v = *(const float4*)(Xs + t * 256 + ((4u * j) ^ swn));
                ss += v.x * v.x + v.y * v.y + v.z * v.z + v.w * v.w;
            }
            const float rno = 1.f / fmaxf(sqrtf(ss), 1e-8f);
            float m = -1e30f;
#pragma unroll
            for (int k = 0; k < 64; k++) m = fmaxf(m, Atm[k * 132 + t]);
            const float ml = m * rno;
            float sum = 0.f;
#pragma unroll
            for (int k = 0; k < 64; k++) {
                float e = __expf(Atm[k * 132 + t] * rno - ml);
                sum += e;
                Atm[k * 132 + t] = e;
            }
            const float inv = 1.f / sum;
#pragma unroll
            for (int k = 0; k < 64; k++)
                AtU[k * 132 + t] = tf32c(Atm[k * 132 + t] * inv);
        }
        __syncthreads();

        // ---- GEMM2: E^T[k][d] += sum_n At[k][n] * Xs[n][d] ----
        {
            const uint32_t swB = (uint32_t)tig << 2;
#pragma unroll 2
            for (int s = 0; s < 16; s++) {
                const int nq = 8 * s + tig;
                uint32_t A2[2][4];
#pragma unroll
                for (int mt = 0; mt < 2; mt++) {
                    const uint32_t* ap = AtU + (K0 + 16 * mt + gid) * 132;
                    A2[mt][0] = ap[nq];            A2[mt][1] = ap[8 * 132 + nq];
                    A2[mt][2] = ap[nq + 4];        A2[mt][3] = ap[8 * 132 + nq + 4];
                }
                const uint32_t* b0p = XsU + nq * 256;
                const uint32_t* b1p = XsU + (nq + 4) * 256;
#pragma unroll
                for (int nt = 0; nt < 8; nt++) {
                    uint32_t dc = db + 8 * nt + gid;
                    uint32_t bf[2];
                    bf[0] = b0p[dc ^ swB];
                    bf[1] = b1p[dc ^ swB ^ 16u];
                    mma8(E2[0][nt], A2[0], bf);
                    mma8(E2[1][nt], A2[1], bf);
                }
            }
        }

        // ---- S-fold: warps 4-7 sum columns of At (normalized A) ----
        if (t >= 128) {
            int tt = t - 128;
            const float* arow = Atm + (tt >> 1) * 132 + (tt & 1) * 64;
            float s = 0.f;
#pragma unroll
            for (int q = 0; q < 64; q++) s += arow[q];
            sS += s;
        }
    }

    // ---- write E^T slab + S ----
    float* slab = g_part + ((size_t)(b * GN + gx)) * Kk * Dd;
#pragma unroll
    for (int mt = 0; mt < 2; mt++)
#pragma unroll
        for (int nt = 0; nt < 8; nt++) {
            int kq = K0 + 16 * mt + gid;
            int dc = db + 8 * nt + 2 * tig;
            *(float2*)(slab + kq * 256 + dc)       = make_float2(E2[mt][nt][0], E2[mt][nt][1]);
            *(float2*)(slab + (kq + 8) * 256 + dc) = make_float2(E2[mt][nt][2], E2[mt][nt][3]);
        }
    if (t >= 128) {
        int tt = t - 128;
        float o = __shfl_xor_sync(0xffffffffu, sS, 1);
        if ((tt & 1) == 0) atomicAdd(&g_S[b * Kk + (tt >> 1)], sS + o);
    }
}

// ---------------- finalize: sum 4 slabs, subtract S*C ----------------
__global__ void fin_kernel(const float* __restrict__ Craw, float* __restrict__ out) {
    int i = blockIdx.x * blockDim.x + threadIdx.x;   // float4 index
    int idx = i * 4;
    int b = idx >> 14;
    int r = idx & 16383;
    int k = r >> 8;
    const float4* P = (const float4*)g_part;
    int s4 = (Kk * Dd) >> 2;
    int base = b * GN * s4 + (r >> 2);
    float4 s = make_float4(0.f, 0.f, 0.f, 0.f);
#pragma unroll
    for (int g = 0; g < GN; g++) {
        float4 pv = P[base + g * s4];
        s.x += pv.x; s.y += pv.y; s.z += pv.z; s.w += pv.w;
    }
    float Sv = g_S[b * Kk + k];
    float4 c = ((const float4*)Craw)[r >> 2];
    s.x -= Sv * c.x; s.y -= Sv * c.y; s.z -= Sv * c.z; s.w -= Sv * c.w;
    ((float4*)out)[i] = s;
}

extern "C" void kernel_launch(void* const* d_in, const int* in_sizes, int n_in,
                              void* d_out, int out_size) {
    const float* X = (const float*)d_in[0];
    const float* C = (const float*)d_in[1];
    float* out = (float*)d_out;

    cudaFuncSetAttribute(main_kernel, cudaFuncAttributeMaxDynamicSharedMemorySize, SMEM_BYTES);

    prep_kernel<<<2, 1024>>>(C);
    main_kernel<<<dim3(GN, Bn), NTH, SMEM_BYTES>>>(X);
    fin_kernel<<<(Bn * Kk * Dd / 4 + 255) / 256, 256>>>(C, out);
}

// round 15
// speedup vs baseline: 4.5590x; 1.1712x over previous
#include <cuda_runtime.h>
#include <cstdint>

// Problem: B=32, D=256, N=4096 (H*W), K=64
constexpr int Bn = 32, Dd = 256, Nn = 4096, Kk = 64;
constexpr int TN = 128, TILES = 8, GN = 4, NTH = 256;

// smem float-word offsets
constexpr int XS = 0;          // Xs [128n][256d], xor-swizzled, 32768 words
constexpr int CT = 32768;      // Ct [64k][256d], xor-swizzled, 16384 words
constexpr int AT = 49152;      // At [64k][stride 132], 8448 words (cols 128..131 = scratch)
constexpr int NP = 57600;      // per-thread sumsq partials, 256 words
constexpr int SMW = 57856;
constexpr int SMEM_BYTES = SMW * 4;   // 231424 <= 232448

__device__ float g_Sp[Bn * GN * Kk];                   // per-CTA S partials
__device__ float g_part[(size_t)Bn * GN * Kk * Dd];   // 8MB per-CTA E^T slabs [k][d]

static __device__ __forceinline__ uint32_t tf32c(float f) {
    uint32_t r;
    asm("cvt.rna.tf32.f32 %0, %1;" : "=r"(r) : "f"(f));
    return r;
}

// D += A(16x8) * B(8x8), tf32 inputs, f32 accumulate
static __device__ __forceinline__ void mma8(float* d, const uint32_t* a, const uint32_t* b) {
    asm volatile("mma.sync.aligned.m16n8k8.row.col.f32.tf32.tf32.f32 "
                 "{%0,%1,%2,%3}, {%4,%5,%6,%7}, {%8,%9}, {%0,%1,%2,%3};"
                 : "+f"(d[0]), "+f"(d[1]), "+f"(d[2]), "+f"(d[3])
                 : "r"(a[0]), "r"(a[1]), "r"(a[2]), "r"(a[3]), "r"(b[0]), "r"(b[1]));
}

// ---------------- main fused kernel (mma.sync tf32) ----------------
__global__ __launch_bounds__(NTH, 1) void main_kernel(const float* __restrict__ X,
                                                      const float* __restrict__ C) {
    extern __shared__ float sm[];
    float*    Xs   = sm + XS;
    float*    Ct   = sm + CT;
    float*    Atm  = sm + AT;
    float*    NPp  = sm + NP;
    uint32_t* XsU  = (uint32_t*)Xs;
    uint32_t* CtU  = (uint32_t*)Ct;
    uint32_t* AtU  = (uint32_t*)Atm;

    const int b = blockIdx.y, gx = blockIdx.x;
    const int t = threadIdx.x, w = t >> 5, lane = t & 31;
    const int gid = lane >> 2, tig = lane & 3;
    const float* Xb = X + (size_t)b * Dd * Nn;

    // ---- in-CTA codeword normalization: Ct[k][d ^ 4*(k&7)] = tf32(C[k][:]/||C[k]||) ----
#pragma unroll
    for (int r = 0; r < 8; r++) {
        int k = w * 8 + r;
        const float* row = C + k * Dd;
        float v[8], ss = 0.f;
#pragma unroll
        for (int j = 0; j < 8; j++) { v[j] = row[lane + 32 * j]; ss += v[j] * v[j]; }
#pragma unroll
        for (int o = 16; o > 0; o >>= 1) ss += __shfl_xor_sync(0xffffffffu, ss, o);
        float rs = 1.f / fmaxf(sqrtf(ss), 1e-8f);
        const uint32_t swk = (uint32_t)(k & 7) << 2;
#pragma unroll
        for (int j = 0; j < 8; j++) {
            uint32_t d = lane + 32 * j;
            CtU[k * 256 + (d ^ swk)] = tf32c(v[j] * rs);
        }
    }

    // GEMM1 warp map: 32n x 32k per warp
    const int M0 = (w & 3) * 32, kb = (w >> 2) * 32;
    // GEMM2 warp map: 32k x 64d per warp
    const int K0 = (w & 1) * 32, db = (w >> 1) * 64;

    float E2[2][8][4];
#pragma unroll
    for (int i = 0; i < 2; i++)
#pragma unroll
        for (int j = 0; j < 8; j++)
#pragma unroll
            for (int q = 0; q < 4; q++) E2[i][j][q] = 0.f;
    float sS = 0.f;   // per-thread S partial: k = t>>2, n-quarter = t&3

    for (int tau = 0; tau < TILES; tau++) {
        const int n0 = (gx * TILES + tau) * TN;
        __syncthreads();   // Xs/At reusable

        // ---- load Xs[n][d] = tf32(X[b][d][n0+n]) + accumulate sumsq ----
        {
            const int gq = t >> 7, nl = t & 127;
            const uint32_t swn = (nl & 7) << 2;
            float ss = 0.f;
#pragma unroll 8
            for (int r = 0; r < 256; r += 8) {
                int d0 = r + gq * 4;
                const float* src = Xb + (size_t)d0 * Nn + n0 + nl;
                float f0 = src[0], f1 = src[Nn], f2 = src[2 * Nn], f3 = src[3 * Nn];
                ss += f0 * f0 + f1 * f1 + f2 * f2 + f3 * f3;
                uint4 o;
                o.x = tf32c(f0); o.y = tf32c(f1); o.z = tf32c(f2); o.w = tf32c(f3);
                *(uint4*)(XsU + nl * 256 + ((uint32_t)d0 ^ swn)) = o;
            }
            NPp[t] = ss;
        }
        __syncthreads();

        // ---- GEMM1: L[n][k] = sum_d Xs[n][d] * Ct[k][d], frags -> At[k][n] (raw) ----
        {
            float D1[2][4][4];
#pragma unroll
            for (int i = 0; i < 2; i++)
#pragma unroll
                for (int j = 0; j < 4; j++)
#pragma unroll
                    for (int q = 0; q < 4; q++) D1[i][j][q] = 0.f;

            const uint32_t swA = (uint32_t)gid << 2;
#pragma unroll 4
            for (int s = 0; s < 32; s++) {
                const uint32_t c0 = 8 * s + tig;
                const uint32_t t1 = c0 ^ swA, t2 = t1 ^ 4u;
                uint32_t A[2][4], Bf[4][2];
#pragma unroll
                for (int mt = 0; mt < 2; mt++) {
                    const uint32_t* rp = XsU + (M0 + 16 * mt + gid) * 256;
                    A[mt][0] = rp[t1];        A[mt][1] = rp[2048 + t1];
                    A[mt][2] = rp[t2];        A[mt][3] = rp[2048 + t2];
                }
#pragma unroll
                for (int kt = 0; kt < 4; kt++) {
                    const uint32_t* cp = CtU + (kb + 8 * kt + gid) * 256;
                    Bf[kt][0] = cp[t1];       Bf[kt][1] = cp[t2];
                }
#pragma unroll
                for (int mt = 0; mt < 2; mt++)
#pragma unroll
                    for (int kt = 0; kt < 4; kt++)
                        mma8(D1[mt][kt], A[mt], Bf[kt]);
            }
#pragma unroll
            for (int mt = 0; mt < 2; mt++)
#pragma unroll
                for (int kt = 0; kt < 4; kt++) {
                    int kq = kb + 8 * kt + 2 * tig;
                    int nq = M0 + 16 * mt + gid;
                    Atm[kq * 132 + nq]           = D1[mt][kt][0];
                    Atm[(kq + 1) * 132 + nq]     = D1[mt][kt][1];
                    Atm[kq * 132 + nq + 8]       = D1[mt][kt][2];
                    Atm[(kq + 1) * 132 + nq + 8] = D1[mt][kt][3];
                }
        }
        __syncthreads();

        // ---- softmax pass A: thread owns (n = t&127, k-half = t>>7); no max-sub (|L|<=1) ----
        float ev[32];
        {
            const int n = t & 127, kh = t >> 7;
            const float ssq = NPp[n] + NPp[n + 128];
            const float rno = rsqrtf(fmaxf(ssq, 1e-16f));
            float psum = 0.f;
#pragma unroll
            for (int j = 0; j < 32; j++) {
                float v = Atm[(32 * kh + j) * 132 + n];
                float e = __expf(v * rno);
                ev[j] = e;
                psum += e;
            }
            Atm[(t >> 2) * 132 + 128 + (t & 3)] = psum;   // scratch in At padding
        }
        __syncthreads();

        // ---- softmax pass B: normalize, write tf32 A^T in place ----
        {
            const int n = t & 127, kh = t >> 7;
            float s0 = Atm[(n >> 2) * 132 + 128 + (n & 3)];
            int n2 = n + 128;
            float s1 = Atm[(n2 >> 2) * 132 + 128 + (n2 & 3)];
            const float inv = 1.f / (s0 + s1);
#pragma unroll
            for (int j = 0; j < 32; j++)
                AtU[(32 * kh + j) * 132 + n] = tf32c(ev[j] * inv);
        }
        __syncthreads();

        // ---- GEMM2: E^T[k][d] += sum_n At[k][n] * Xs[n][d] ----
        {
            const uint32_t swB = (uint32_t)tig << 2;
#pragma unroll 2
            for (int s = 0; s < 16; s++) {
                const int nq = 8 * s + tig;
                uint32_t A2[2][4];
#pragma unroll
                for (int mt = 0; mt < 2; mt++) {
                    const uint32_t* ap = AtU + (K0 + 16 * mt + gid) * 132;
                    A2[mt][0] = ap[nq];            A2[mt][1] = ap[8 * 132 + nq];
                    A2[mt][2] = ap[nq + 4];        A2[mt][3] = ap[8 * 132 + nq + 4];
                }
                const uint32_t* b0p = XsU + nq * 256;
                const uint32_t* b1p = XsU + (nq + 4) * 256;
#pragma unroll
                for (int nt = 0; nt < 8; nt++) {
                    uint32_t dc = db + 8 * nt + gid;
                    uint32_t bf[2];
                    bf[0] = b0p[dc ^ swB];
                    bf[1] = b1p[dc ^ swB ^ 16u];
                    mma8(E2[0][nt], A2[0], bf);
                    mma8(E2[1][nt], A2[1], bf);
                }
            }
        }

        // ---- S-fold: thread sums 32 n of row k (register accum across tiles) ----
        {
            const int k = t >> 2, q = t & 3;
            const float* arow = Atm + k * 132 + 32 * q;
            float s = 0.f;
#pragma unroll
            for (int j = 0; j < 32; j++) s += arow[(j + 8 * q) & 31];
            sS += s;
        }
    }

    // ---- write E^T slab + per-CTA S partials (no atomics) ----
    float* slab = g_part + ((size_t)(b * GN + gx)) * Kk * Dd;
#pragma unroll
    for (int mt = 0; mt < 2; mt++)
#pragma unroll
        for (int nt = 0; nt < 8; nt++) {
            int kq = K0 + 16 * mt + gid;
            int dc = db + 8 * nt + 2 * tig;
            *(float2*)(slab + kq * 256 + dc)       = make_float2(E2[mt][nt][0], E2[mt][nt][1]);
            *(float2*)(slab + (kq + 8) * 256 + dc) = make_float2(E2[mt][nt][2], E2[mt][nt][3]);
        }
    sS += __shfl_xor_sync(0xffffffffu, sS, 1);
    sS += __shfl_xor_sync(0xffffffffu, sS, 2);
    if ((t & 3) == 0) g_Sp[(b * GN + gx) * Kk + (t >> 2)] = sS;
}

// ---------------- finalize: sum 4 slabs, subtract S*C ----------------
__global__ void fin_kernel(const float* __restrict__ Craw, float* __restrict__ out) {
    int i = blockIdx.x * blockDim.x + threadIdx.x;   // float4 index
    int idx = i * 4;
    int b = idx >> 14;
    int r = idx & 16383;
    int k = r >> 8;
    const float4* P = (const float4*)g_part;
    int s4 = (Kk * Dd) >> 2;
    int base = b * GN * s4 + (r >> 2);
    float4 s = make_float4(0.f, 0.f, 0.f, 0.f);
    float Sv = 0.f;
#pragma unroll
    for (int g = 0; g < GN; g++) {
        float4 pv = P[base + g * s4];
        s.x += pv.x; s.y += pv.y; s.z += pv.z; s.w += pv.w;
        Sv += g_Sp[(b * GN + g) * Kk + k];
    }
    float4 c = ((const float4*)Craw)[r >> 2];
    s.x -= Sv * c.x; s.y -= Sv * c.y; s.z -= Sv * c.z; s.w -= Sv * c.w;
    ((float4*)out)[i] = s;
}

extern "C" void kernel_launch(void* const* d_in, const int* in_sizes, int n_in,
                              void* d_out, int out_size) {
    const float* X = (const float*)d_in[0];
    const float* C = (const float*)d_in[1];
    float* out = (float*)d_out;

    cudaFuncSetAttribute(main_kernel, cudaFuncAttributeMaxDynamicSharedMemorySize, SMEM_BYTES);

    main_kernel<<<dim3(GN, Bn), NTH, SMEM_BYTES>>>(X, C);
    fin_kernel<<<(Bn * Kk * Dd / 4 + 255) / 256, 256>>>(C, out);
}

// round 16
// speedup vs baseline: 4.6384x; 1.0174x over previous
#include <cuda_runtime.h>
#include <cstdint>

// Problem: B=32, D=256, N=4096 (H*W), K=64
constexpr int Bn = 32, Dd = 256, Nn = 4096, Kk = 64;
constexpr int TN = 128, TILES = 8, GN = 4, NTH = 256;

// smem float-word offsets
constexpr int XS = 0;          // Xs [128n][256d], swizzled, 32768 words
constexpr int CT = 32768;      // Ct [64k][256d], swizzled, 16384 words
constexpr int AT = 49152;      // At [64k][stride 132], 8448 words
constexpr int NP = 57600;      // per-thread sumsq partials, 256 words
constexpr int RS = 57856;      // row-sum exchange [2][128], 256 words
constexpr int SMW = 58112;
constexpr int SMEM_BYTES = SMW * 4;   // 232448 (= 227 KB cap)

__device__ float g_Sp[Bn * GN * Kk];                   // per-CTA S partials
__device__ float g_part[(size_t)Bn * GN * Kk * Dd];   // 8MB per-CTA E^T slabs [k][d]

static __device__ __forceinline__ uint32_t tf32c(float f) {
    uint32_t r;
    asm("cvt.rna.tf32.f32 %0, %1;" : "=r"(r) : "f"(f));
    return r;
}

// D += A(16x8) * B(8x8), tf32 inputs, f32 accumulate
static __device__ __forceinline__ void mma8(float* d, const uint32_t* a, const uint32_t* b) {
    asm volatile("mma.sync.aligned.m16n8k8.row.col.f32.tf32.tf32.f32 "
                 "{%0,%1,%2,%3}, {%4,%5,%6,%7}, {%8,%9}, {%0,%1,%2,%3};"
                 : "+f"(d[0]), "+f"(d[1]), "+f"(d[2]), "+f"(d[3])
                 : "r"(a[0]), "r"(a[1]), "r"(a[2]), "r"(a[3]), "r"(b[0]), "r"(b[1]));
}

// swizzle mask for row n (applies to word-index bits [2:5))
static __device__ __forceinline__ uint32_t rmask(int n) {
    return ((uint32_t)(n & 7) << 2) ^ ((uint32_t)(n & 3) << 3);
}

// ---------------- main fused kernel (mma.sync tf32) ----------------
__global__ __launch_bounds__(NTH, 1) void main_kernel(const float* __restrict__ X,
                                                      const float* __restrict__ C) {
    extern __shared__ float sm[];
    float*    Xs   = sm + XS;
    float*    Atm  = sm + AT;
    float*    NPp  = sm + NP;
    float*    Rs   = sm + RS;
    uint32_t* XsU  = (uint32_t*)Xs;
    uint32_t* CtU  = (uint32_t*)(sm + CT);
    uint32_t* AtU  = (uint32_t*)Atm;

    const int b = blockIdx.y, gx = blockIdx.x;
    const int t = threadIdx.x, w = t >> 5, lane = t & 31;
    const int gid = lane >> 2, tig = lane & 3;
    const float* Xb = X + (size_t)b * Dd * Nn;

    // ---- in-CTA codeword normalization: Ct[k][d ^ m(k)] = tf32(C[k][:]/||C[k]||) ----
#pragma unroll
    for (int r = 0; r < 8; r++) {
        int k = w * 8 + r;
        const float* row = C + k * Dd;
        float v[8], ss = 0.f;
#pragma unroll
        for (int j = 0; j < 8; j++) { v[j] = row[lane + 32 * j]; ss += v[j] * v[j]; }
#pragma unroll
        for (int o = 16; o > 0; o >>= 1) ss += __shfl_xor_sync(0xffffffffu, ss, o);
        float rs = 1.f / fmaxf(sqrtf(ss), 1e-8f);
        const uint32_t mk = rmask(k);
#pragma unroll
        for (int j = 0; j < 8; j++) {
            uint32_t d = lane + 32 * j;
            CtU[k * 256 + (d ^ mk)] = tf32c(v[j] * rs);
        }
    }

    // GEMM1 warp map: 32n x 32k per warp ; GEMM2: 32k x 64d per warp
    const int M0 = (w & 3) * 32, kb = (w >> 2) * 32, kh = w >> 2;
    const int K0 = (w & 1) * 32, db = (w >> 1) * 64;
    const uint32_t mA = rmask(gid);          // row masks for GEMM1 A/B reads (row&7==gid)

    float E2[2][8][4];
#pragma unroll
    for (int i = 0; i < 2; i++)
#pragma unroll
        for (int j = 0; j < 8; j++)
#pragma unroll
            for (int q = 0; q < 4; q++) E2[i][j][q] = 0.f;
    float sS = 0.f;

    for (int tau = 0; tau < TILES; tau++) {
        const int n0 = (gx * TILES + tau) * TN;
        __syncthreads();   // Xs/At reusable (prev GEMM2 + S-fold done)

        // ---- load Xs[n][d] = tf32(X[b][d][n0+n]) + accumulate sumsq ----
        {
            const int gq = t >> 7, nl = t & 127;
            const uint32_t mn = rmask(nl);
            float ss = 0.f;
#pragma unroll 8
            for (int r = 0; r < 256; r += 8) {
                int d0 = r + gq * 4;
                const float* src = Xb + (size_t)d0 * Nn + n0 + nl;
                float f0 = src[0], f1 = src[Nn], f2 = src[2 * Nn], f3 = src[3 * Nn];
                ss += f0 * f0 + f1 * f1 + f2 * f2 + f3 * f3;
                uint4 o;
                o.x = tf32c(f0); o.y = tf32c(f1); o.z = tf32c(f2); o.w = tf32c(f3);
                *(uint4*)(XsU + nl * 256 + ((uint32_t)d0 ^ mn)) = o;
            }
            NPp[t] = ss;
        }
        __syncthreads();

        // ---- GEMM1: L[n][k] = sum_d Xs[n][d]*Ct[k][d]; fused exp + row-sum epilogue ----
        float D1[2][4][4];
        {
#pragma unroll
            for (int i = 0; i < 2; i++)
#pragma unroll
                for (int j = 0; j < 4; j++)
#pragma unroll
                    for (int q = 0; q < 4; q++) D1[i][j][q] = 0.f;

#pragma unroll 4
            for (int s = 0; s < 32; s++) {
                const uint32_t t1 = (uint32_t)(8 * s + tig) ^ mA, t2 = t1 ^ 4u;
                uint32_t A[2][4], Bf[4][2];
#pragma unroll
                for (int mt = 0; mt < 2; mt++) {
                    const uint32_t* rp = XsU + (M0 + 16 * mt + gid) * 256;
                    A[mt][0] = rp[t1];        A[mt][1] = rp[2048 + t1];
                    A[mt][2] = rp[t2];        A[mt][3] = rp[2048 + t2];
                }
#pragma unroll
                for (int kt = 0; kt < 4; kt++) {
                    const uint32_t* cp = CtU + (kb + 8 * kt + gid) * 256;
                    Bf[kt][0] = cp[t1];       Bf[kt][1] = cp[t2];
                }
#pragma unroll
                for (int mt = 0; mt < 2; mt++)
#pragma unroll
                    for (int kt = 0; kt < 4; kt++)
                        mma8(D1[mt][kt], A[mt], Bf[kt]);
            }

            // epilogue: e = exp(L * rno(n)); partial row sums
            float rsq[2][2], rsum[2][2];
#pragma unroll
            for (int mt = 0; mt < 2; mt++) {
                int nr = M0 + 16 * mt + gid;
                rsq[mt][0] = rsqrtf(fmaxf(NPp[nr] + NPp[nr + 128], 1e-16f));
                rsq[mt][1] = rsqrtf(fmaxf(NPp[nr + 8] + NPp[nr + 136], 1e-16f));
                rsum[mt][0] = 0.f; rsum[mt][1] = 0.f;
            }
#pragma unroll
            for (int mt = 0; mt < 2; mt++)
#pragma unroll
                for (int kt = 0; kt < 4; kt++) {
                    float e0 = __expf(D1[mt][kt][0] * rsq[mt][0]);
                    float e1 = __expf(D1[mt][kt][1] * rsq[mt][0]);
                    float e2 = __expf(D1[mt][kt][2] * rsq[mt][1]);
                    float e3 = __expf(D1[mt][kt][3] * rsq[mt][1]);
                    D1[mt][kt][0] = e0; D1[mt][kt][1] = e1;
                    D1[mt][kt][2] = e2; D1[mt][kt][3] = e3;
                    rsum[mt][0] += e0 + e1;
                    rsum[mt][1] += e2 + e3;
                }
#pragma unroll
            for (int mt = 0; mt < 2; mt++)
#pragma unroll
                for (int h = 0; h < 2; h++) {
                    rsum[mt][h] += __shfl_xor_sync(0xffffffffu, rsum[mt][h], 1);
                    rsum[mt][h] += __shfl_xor_sync(0xffffffffu, rsum[mt][h], 2);
                }
            if (tig == 0) {
                Rs[kh * 128 + M0 + gid]      = rsum[0][0];
                Rs[kh * 128 + M0 + gid + 8]  = rsum[0][1];
                Rs[kh * 128 + M0 + gid + 16] = rsum[1][0];
                Rs[kh * 128 + M0 + gid + 24] = rsum[1][1];
            }
        }
        __syncthreads();

        // ---- normalize + store tf32 A^T into At ----
        {
            float inv[2][2];
#pragma unroll
            for (int mt = 0; mt < 2; mt++) {
                int nr = M0 + 16 * mt + gid;
                inv[mt][0] = 1.f / (Rs[nr] + Rs[128 + nr]);
                inv[mt][1] = 1.f / (Rs[nr + 8] + Rs[136 + nr]);
            }
#pragma unroll
            for (int mt = 0; mt < 2; mt++)
#pragma unroll
                for (int kt = 0; kt < 4; kt++) {
                    int kq = kb + 8 * kt + 2 * tig;
                    int nq = M0 + 16 * mt + gid;
                    AtU[kq * 132 + nq]           = tf32c(D1[mt][kt][0] * inv[mt][0]);
                    AtU[(kq + 1) * 132 + nq]     = tf32c(D1[mt][kt][1] * inv[mt][0]);
                    AtU[kq * 132 + nq + 8]       = tf32c(D1[mt][kt][2] * inv[mt][1]);
                    AtU[(kq + 1) * 132 + nq + 8] = tf32c(D1[mt][kt][3] * inv[mt][1]);
                }
        }
        __syncthreads();

        // ---- GEMM2: E^T[k][d] += sum_n At[k][n] * Xs[n][d] ----
        {
            const uint32_t m1 = ((uint32_t)tig << 2) ^ ((uint32_t)tig << 3);
            const uint32_t m2 = m1 ^ 16u;
#pragma unroll 2
            for (int s = 0; s < 16; s++) {
                const int nq = 8 * s + tig;
                uint32_t A2[2][4];
#pragma unroll
                for (int mt = 0; mt < 2; mt++) {
                    const uint32_t* ap = AtU + (K0 + 16 * mt + gid) * 132;
                    A2[mt][0] = ap[nq];            A2[mt][1] = ap[8 * 132 + nq];
                    A2[mt][2] = ap[nq + 4];        A2[mt][3] = ap[8 * 132 + nq + 4];
                }
                const uint32_t* b0p = XsU + nq * 256;
                const uint32_t* b1p = b0p + 4 * 256;
#pragma unroll
                for (int nt = 0; nt < 8; nt++) {
                    uint32_t dc = (uint32_t)(db + 8 * nt + gid);
                    uint32_t bf[2];
                    bf[0] = b0p[dc ^ m1];
                    bf[1] = b1p[dc ^ m2];
                    mma8(E2[0][nt], A2[0], bf);
                    mma8(E2[1][nt], A2[1], bf);
                }
            }
        }

        // ---- S-fold: thread sums 32 n of row k (register accum across tiles) ----
        {
            const int k = t >> 2, q = t & 3;
            const float* arow = Atm + k * 132 + 32 * q;
            float s = 0.f;
#pragma unroll
            for (int j = 0; j < 32; j++) s += arow[(j + 8 * q) & 31];
            sS += s;
        }
    }

    // ---- write E^T slab + per-CTA S partials (no atomics) ----
    float* slab = g_part + ((size_t)(b * GN + gx)) * Kk * Dd;
#pragma unroll
    for (int mt = 0; mt < 2; mt++)
#pragma unroll
        for (int nt = 0; nt < 8; nt++) {
            int kq = K0 + 16 * mt + gid;
            int dc = db + 8 * nt + 2 * tig;
            *(float2*)(slab + kq * 256 + dc)       = make_float2(E2[mt][nt][0], E2[mt][nt][1]);
            *(float2*)(slab + (kq + 8) * 256 + dc) = make_float2(E2[mt][nt][2], E2[mt][nt][3]);
        }
    sS += __shfl_xor_sync(0xffffffffu, sS, 1);
    sS += __shfl_xor_sync(0xffffffffu, sS, 2);
    if ((t & 3) == 0) g_Sp[(b * GN + gx) * Kk + (t >> 2)] = sS;
}

// ---------------- finalize: sum 4 slabs, subtract S*C ----------------
__global__ void fin_kernel(const float* __restrict__ Craw, float* __restrict__ out) {
    int i = blockIdx.x * blockDim.x + threadIdx.x;   // float4 index
    int idx = i * 4;
    int b = idx >> 14;
    int r = idx & 16383;
    int k = r >> 8;
    const float4* P = (const float4*)g_part;
    int s4 = (Kk * Dd) >> 2;
    int base = b * GN * s4 + (r >> 2);
    float4 s = make_float4(0.f, 0.f, 0.f, 0.f);
    float Sv = 0.f;
#pragma unroll
    for (int g = 0; g < GN; g++) {
        float4 pv = P[base + g * s4];
        s.x += pv.x; s.y += pv.y; s.z += pv.z; s.w += pv.w;
        Sv += g_Sp[(b * GN + g) * Kk + k];
    }
    float4 c = ((const float4*)Craw)[r >> 2];
    s.x -= Sv * c.x; s.y -= Sv * c.y; s.z -= Sv * c.z; s.w -= Sv * c.w;
    ((float4*)out)[i] = s;
}

extern "C" void kernel_launch(void* const* d_in, const int* in_sizes, int n_in,
                              void* d_out, int out_size) {
    const float* X = (const float*)d_in[0];
    const float* C = (const float*)d_in[1];
    float* out = (float*)d_out;

    cudaFuncSetAttribute(main_kernel, cudaFuncAttributeMaxDynamicSharedMemorySize, SMEM_BYTES);

    main_kernel<<<dim3(GN, Bn), NTH, SMEM_BYTES>>>(X, C);
    fin_kernel<<<(Bn * Kk * Dd / 4 + 255) / 256, 256>>>(C, out);
}